// round 1
// baseline (speedup 1.0000x reference)
#include <cuda_runtime.h>
#include <math.h>

#define BB 4
#define TT 2048
#define DD 768
#define NH 12
#define HD 64
#define WIN 64
#define TD3 (3*DD)

// scratch (device globals: allocation-free rule)
__device__ float g_qkv[(size_t)BB*TT*TD3];   // [B,T,3D]  ~75.5 MB
__device__ float g_attn[(size_t)BB*TT*DD];   // [B,T,D]   ~25 MB

typedef unsigned long long u64;

__device__ __forceinline__ u64 pk2(float lo, float hi){
    u64 r; asm("mov.b64 %0,{%1,%2};" : "=l"(r) : "f"(lo), "f"(hi)); return r;
}
__device__ __forceinline__ u64 fma2(u64 a, u64 b, u64 c){
    u64 d; asm("fma.rn.f32x2 %0,%1,%2,%3;" : "=l"(d) : "l"(a), "l"(b), "l"(c)); return d;
}
__device__ __forceinline__ float2 up2(u64 v){
    float2 f; asm("mov.b64 {%0,%1},%2;" : "=f"(f.x), "=f"(f.y) : "l"(v)); return f;
}

// ---------------------------------------------------------------------------
// GEMM: C[m,n] = sum_k A[m,k] * W[n,k]   (both K-major, "NT")
// M%128==0, N%128==0, K%16==0. 128x128 tile, 256 thr, 8x8/thread via f32x2.
// ---------------------------------------------------------------------------
__global__ void __launch_bounds__(256, 2)
gemm_nt(const float* __restrict__ A, const float* __restrict__ W,
        float* __restrict__ C, int M, int N, int K)
{
    __shared__ __align__(16) float As[16][132];  // [k][m]
    __shared__ __align__(16) float Bs[16][132];  // [k][n]

    const int tid = threadIdx.x;
    const int bm = blockIdx.y * 128;
    const int bn = blockIdx.x * 128;
    const int tx = tid & 15;     // 16 n-groups of 8
    const int ty = tid >> 4;     // 16 m-groups of 8

    u64 acc[8][4];
#pragma unroll
    for (int i = 0; i < 8; i++)
#pragma unroll
        for (int j = 0; j < 4; j++) acc[i][j] = 0ull;

    const int lrow = tid >> 2;          // 0..63
    const int lk4  = (tid & 3) * 4;     // 0,4,8,12
    const float* Ap = A + (size_t)(bm + lrow) * K + lk4;
    const float* Wp = W + (size_t)(bn + lrow) * K + lk4;
    const size_t rstep = (size_t)64 * K;

    for (int k0 = 0; k0 < K; k0 += 16) {
        float4 va0 = *(const float4*)(Ap + k0);
        float4 va1 = *(const float4*)(Ap + k0 + rstep);
        float4 vb0 = *(const float4*)(Wp + k0);
        float4 vb1 = *(const float4*)(Wp + k0 + rstep);

        As[lk4+0][lrow]    = va0.x; As[lk4+1][lrow]    = va0.y;
        As[lk4+2][lrow]    = va0.z; As[lk4+3][lrow]    = va0.w;
        As[lk4+0][lrow+64] = va1.x; As[lk4+1][lrow+64] = va1.y;
        As[lk4+2][lrow+64] = va1.z; As[lk4+3][lrow+64] = va1.w;
        Bs[lk4+0][lrow]    = vb0.x; Bs[lk4+1][lrow]    = vb0.y;
        Bs[lk4+2][lrow]    = vb0.z; Bs[lk4+3][lrow]    = vb0.w;
        Bs[lk4+0][lrow+64] = vb1.x; Bs[lk4+1][lrow+64] = vb1.y;
        Bs[lk4+2][lrow+64] = vb1.z; Bs[lk4+3][lrow+64] = vb1.w;
        __syncthreads();

#pragma unroll
        for (int k = 0; k < 16; k++) {
            float4 a0 = *(const float4*)&As[k][ty*8];
            float4 a1 = *(const float4*)&As[k][ty*8+4];
            ulonglong2 b01 = *(const ulonglong2*)&Bs[k][tx*8];
            ulonglong2 b23 = *(const ulonglong2*)&Bs[k][tx*8+4];
            u64 bp[4] = { b01.x, b01.y, b23.x, b23.y };
            float aa[8] = { a0.x, a0.y, a0.z, a0.w, a1.x, a1.y, a1.z, a1.w };
#pragma unroll
            for (int i = 0; i < 8; i++) {
                u64 ad = pk2(aa[i], aa[i]);
#pragma unroll
                for (int j = 0; j < 4; j++)
                    acc[i][j] = fma2(ad, bp[j], acc[i][j]);
            }
        }
        __syncthreads();
    }

#pragma unroll
    for (int i = 0; i < 8; i++) {
        float* Cp = C + (size_t)(bm + ty*8 + i) * N + bn + tx*8;
        float2 p0 = up2(acc[i][0]), p1 = up2(acc[i][1]);
        float2 p2 = up2(acc[i][2]), p3 = up2(acc[i][3]);
        *(float4*)Cp       = make_float4(p0.x, p0.y, p1.x, p1.y);
        *(float4*)(Cp + 4) = make_float4(p2.x, p2.y, p3.x, p3.y);
    }
}

// ---------------------------------------------------------------------------
// RoPE in-place on q and k parts of g_qkv. One warp per (b,t,head).
// out[2j]   = x[j]*cos - x[j+32]*sin
// out[2j+1] = x[j]*sin + x[j+32]*cos,  ang = t * 10000^(-j/32)
// ---------------------------------------------------------------------------
__global__ void rope_kernel(float* __restrict__ qkv)
{
    int gw   = (blockIdx.x * blockDim.x + threadIdx.x) >> 5;
    int lane = threadIdx.x & 31;
    if (gw >= BB * TT * NH) return;
    int h = gw % NH;
    int t = (gw / NH) % TT;
    int b = gw / (NH * TT);

    float inv = (float)pow(10000.0, -(double)lane / 32.0);
    float ang = (float)t * inv;
    float sn, cs;
    sincosf(ang, &sn, &cs);

    float* base = qkv + (size_t)(b * TT + t) * TD3 + h * HD;
    // q part (offset 0) and k part (offset DD)
    float qre = base[lane],        qim = base[lane + 32];
    float kre = base[DD + lane],   kim = base[DD + lane + 32];
    __syncwarp();
    base[2*lane]          = qre * cs - qim * sn;
    base[2*lane + 1]      = qre * sn + qim * cs;
    base[DD + 2*lane]     = kre * cs - kim * sn;
    base[DD + 2*lane + 1] = kre * sn + kim * cs;
}

// ---------------------------------------------------------------------------
// Sliding-window attention. One CTA per (64-query tile, head, batch).
// Keys in [q0-64, q0+127] (<=192). smem tiles, shuffle softmax.
// ---------------------------------------------------------------------------
#define ATTN_SMEM_FLOATS (64*68 + 64*200 + 192*68 + 64*200 + 64 + 192)
#define ATTN_SMEM_BYTES  (ATTN_SMEM_FLOATS * 4)

__global__ void __launch_bounds__(256, 1)
attn_kernel(const float* __restrict__ qkv, const int* __restrict__ amask,
            float* __restrict__ out)
{
    extern __shared__ __align__(16) float sm[];
    float* Qt = sm;                    // [64][68]  d-major: Qt[d][q]
    float* Kt = Qt + 64*68;            // [64][200] d-major: Kt[d][k]
    float* Vs = Kt + 64*200;           // [192][68] k-major: Vs[k][d]
    float* Ps = Vs + 192*68;           // [64][200] Ps[q][k] (unnormalized)
    float* Rs = Ps + 64*200;           // [64] row sums
    int*   Ms = (int*)(Rs + 64);       // [192] key pad mask

    const int tid = threadIdx.x;
    const int qb = blockIdx.x, h = blockIdx.y, b = blockIdx.z;
    const int q0 = qb * 64;
    const int ks = max(0, q0 - WIN);
    const int ke = min(TT, q0 + 64 + WIN);
    const int klen = ke - ks;
    const float* qbase = qkv + (size_t)b * TT * TD3;

    // Q transposed: Qt[d][q]
#pragma unroll
    for (int it = 0; it < 4; it++) {
        int idx = tid + it * 256;
        int d4 = idx >> 6, row = idx & 63;
        float4 v = *(const float4*)(qbase + (size_t)(q0+row)*TD3 + h*HD + d4*4);
        Qt[(d4*4+0)*68 + row] = v.x; Qt[(d4*4+1)*68 + row] = v.y;
        Qt[(d4*4+2)*68 + row] = v.z; Qt[(d4*4+3)*68 + row] = v.w;
    }
    // K transposed: Kt[d][k]
#pragma unroll
    for (int it = 0; it < 12; it++) {
        int idx = tid + it * 256;
        int d4 = idx / 192, kk = idx % 192;
        if (kk < klen) {
            float4 v = *(const float4*)(qbase + (size_t)(ks+kk)*TD3 + DD + h*HD + d4*4);
            Kt[(d4*4+0)*200 + kk] = v.x; Kt[(d4*4+1)*200 + kk] = v.y;
            Kt[(d4*4+2)*200 + kk] = v.z; Kt[(d4*4+3)*200 + kk] = v.w;
        }
    }
    // V direct: Vs[k][d]
#pragma unroll
    for (int it = 0; it < 12; it++) {
        int idx = tid + it * 256;
        int kk = idx >> 4, d4 = idx & 15;
        if (kk < klen) {
            float4 v = *(const float4*)(qbase + (size_t)(ks+kk)*TD3 + 2*DD + h*HD + d4*4);
            *(float4*)&Vs[kk*68 + d4*4] = v;
        }
    }
    if (tid < 192) Ms[tid] = (tid < klen) ? amask[b*TT + ks + tid] : 0;
    __syncthreads();

    // ---- scores: each thread 4q x 12k ----
    const int tx = tid & 15;   // k-group
    const int ty = tid >> 4;   // q-group
    float s[4][12];
#pragma unroll
    for (int qi = 0; qi < 4; qi++)
#pragma unroll
        for (int ki = 0; ki < 12; ki++) s[qi][ki] = 0.f;

    for (int d = 0; d < 64; d++) {
        float4 aq = *(const float4*)&Qt[d*68 + ty*4];
        float4 b0 = *(const float4*)&Kt[d*200 + tx*12];
        float4 b1 = *(const float4*)&Kt[d*200 + tx*12 + 4];
        float4 b2 = *(const float4*)&Kt[d*200 + tx*12 + 8];
        float aa[4] = { aq.x, aq.y, aq.z, aq.w };
        float bk[12] = { b0.x,b0.y,b0.z,b0.w, b1.x,b1.y,b1.z,b1.w, b2.x,b2.y,b2.z,b2.w };
#pragma unroll
        for (int qi = 0; qi < 4; qi++)
#pragma unroll
            for (int ki = 0; ki < 12; ki++)
                s[qi][ki] += aa[qi] * bk[ki];
    }

    // ---- mask + softmax (shuffle reduce across the 16 tx lanes) ----
    const float scale = 0.125f;  // 1/sqrt(64)
#pragma unroll
    for (int qi = 0; qi < 4; qi++) {
        int qg = q0 + ty*4 + qi;
        bool ok[12];
        float mx = -1e30f;
#pragma unroll
        for (int ki = 0; ki < 12; ki++) {
            int kk = tx*12 + ki;
            int kg = ks + kk;
            ok[ki] = (kk < klen) && (abs(qg - kg) <= WIN) && (Ms[kk] != 0);
            float sv = s[qi][ki] * scale;
            s[qi][ki] = sv;
            if (ok[ki]) mx = fmaxf(mx, sv);
        }
#pragma unroll
        for (int off = 8; off; off >>= 1)
            mx = fmaxf(mx, __shfl_xor_sync(0xffffffffu, mx, off));
        float sum = 0.f;
#pragma unroll
        for (int ki = 0; ki < 12; ki++) {
            float p = ok[ki] ? __expf(s[qi][ki] - mx) : 0.f;
            s[qi][ki] = p;
            sum += p;
        }
#pragma unroll
        for (int off = 8; off; off >>= 1)
            sum += __shfl_xor_sync(0xffffffffu, sum, off);
#pragma unroll
        for (int ki = 0; ki < 12; ki++)
            Ps[(ty*4+qi)*200 + tx*12 + ki] = s[qi][ki];
        if (tx == 0) Rs[ty*4 + qi] = sum;
    }
    __syncthreads();

    // ---- PV: each thread 4q x 4d ----
    const int tx2 = tid & 15;   // d-group of 4
    const int ty2 = tid >> 4;   // q-group of 4
    float o[4][4];
#pragma unroll
    for (int qi = 0; qi < 4; qi++)
#pragma unroll
        for (int di = 0; di < 4; di++) o[qi][di] = 0.f;

    for (int k = 0; k < klen; k++) {
        float4 vv = *(const float4*)&Vs[k*68 + tx2*4];
        float v4[4] = { vv.x, vv.y, vv.z, vv.w };
        float pq[4];
#pragma unroll
        for (int qi = 0; qi < 4; qi++) pq[qi] = Ps[(ty2*4+qi)*200 + k];
#pragma unroll
        for (int qi = 0; qi < 4; qi++)
#pragma unroll
            for (int di = 0; di < 4; di++)
                o[qi][di] += pq[qi] * v4[di];
    }
#pragma unroll
    for (int qi = 0; qi < 4; qi++) {
        float r = 1.f / fmaxf(Rs[ty2*4 + qi], 1e-30f);
        float4 ov = make_float4(o[qi][0]*r, o[qi][1]*r, o[qi][2]*r, o[qi][3]*r);
        *(float4*)&out[(size_t)(b*TT + q0 + ty2*4 + qi)*DD + h*HD + tx2*4] = ov;
    }
}

// ---------------------------------------------------------------------------
extern "C" void kernel_launch(void* const* d_in, const int* in_sizes, int n_in,
                              void* d_out, int out_size)
{
    const float* hs   = (const float*)d_in[0];
    const int*   am   = (const int*)d_in[1];
    const float* Wqkv = (const float*)d_in[2];
    const float* Wo   = (const float*)d_in[3];
    float* out = (float*)d_out;

    void* p1; cudaGetSymbolAddress(&p1, g_qkv);
    void* p2; cudaGetSymbolAddress(&p2, g_attn);
    float* qkv  = (float*)p1;
    float* attn = (float*)p2;

    cudaFuncSetAttribute(attn_kernel,
                         cudaFuncAttributeMaxDynamicSharedMemorySize,
                         ATTN_SMEM_BYTES);

    // 1) QKV projection: [8192,768] x [2304,768]^T
    dim3 g1(TD3/128, (BB*TT)/128);
    gemm_nt<<<g1, 256>>>(hs, Wqkv, qkv, BB*TT, TD3, DD);

    // 2) RoPE on q,k in place
    rope_kernel<<<(BB*TT*NH*32)/256, 256>>>(qkv);

    // 3) Sliding-window attention
    dim3 ga(TT/64, NH, BB);
    attn_kernel<<<ga, 256, ATTN_SMEM_BYTES>>>(qkv, am, attn);

    // 4) Output projection: [8192,768] x [768,768]^T
    dim3 g2(DD/128, (BB*TT)/128);
    gemm_nt<<<g2, 256>>>(attn, Wo, out, BB*TT, DD, DD);
}